// round 2
// baseline (speedup 1.0000x reference)
#include <cuda_runtime.h>
#include <math.h>
#include <float.h>

// Problem constants
#define BB   8
#define TT   128
#define DD   512
#define MM   256
#define TOPK 8
#define NHH  2
#define DKK  32
#define DPP  16
#define BT   (BB*TT)   // 1024

// ---------------- scratch (static device arrays; no runtime alloc) ----------------
// NOTE: __align__(16) is required — these are accessed through float4*.
__device__ __align__(16) float g_zw  [BT*DKK];
__device__ __align__(16) float g_zr  [BT*DKK];
__device__ __align__(16) float g_kj  [BT*NHH*DD];   // silu(h @ hh_k^T)
__device__ __align__(16) float g_khat[BT*NHH*DD];   // normalized
__device__ __align__(16) float g_vk  [BT*NHH*DD];
__device__ __align__(16) float g_vv  [BT*NHH*DD];
__device__ __align__(16) float g_beta[BT*NHH];
__device__ __align__(16) float g_gate[BT*DD];       // gate logits (sigmoid applied in final GEMM)
__device__ __align__(16) float g_RO  [BT*DD];       // attention readout
__device__           int   g_widx[BT*TOPK];
__device__ __align__(16) float g_ww  [BT*TOPK];
__device__           int   g_ridx[BT*TOPK];

// ---------------- generic fp32 GEMM: C[m,n] = sum_k A[m,k]*B[n,k] ----------------
// act: 0 = none, 1 = silu. gate != nullptr => C *= sigmoid(gate[m,n]).
__global__ void gemm_kernel(const float* __restrict__ A, const float* __restrict__ Bm,
                            float* __restrict__ C, int Mr, int Nr, int Kr,
                            int act, const float* __restrict__ gate)
{
    __shared__ float As[16][68];
    __shared__ float Bs[16][68];
    int tid = threadIdx.x;
    int tx = tid & 15, ty = tid >> 4;
    int bm0 = blockIdx.y * 64, bn0 = blockIdx.x * 64;
    float acc[4][4];
#pragma unroll
    for (int i = 0; i < 4; i++)
#pragma unroll
        for (int j = 0; j < 4; j++) acc[i][j] = 0.f;

    int lrow = tid >> 2;          // 0..63
    int lc4  = (tid & 3) * 4;     // 0,4,8,12

    for (int k0 = 0; k0 < Kr; k0 += 16) {
        float4 a4 = make_float4(0.f, 0.f, 0.f, 0.f);
        float4 b4 = make_float4(0.f, 0.f, 0.f, 0.f);
        int gm = bm0 + lrow;
        if (gm < Mr) a4 = *(const float4*)&A[(size_t)gm * Kr + k0 + lc4];
        int gn = bn0 + lrow;
        if (gn < Nr) b4 = *(const float4*)&Bm[(size_t)gn * Kr + k0 + lc4];
        As[lc4 + 0][lrow] = a4.x; As[lc4 + 1][lrow] = a4.y;
        As[lc4 + 2][lrow] = a4.z; As[lc4 + 3][lrow] = a4.w;
        Bs[lc4 + 0][lrow] = b4.x; Bs[lc4 + 1][lrow] = b4.y;
        Bs[lc4 + 2][lrow] = b4.z; Bs[lc4 + 3][lrow] = b4.w;
        __syncthreads();
#pragma unroll
        for (int kk = 0; kk < 16; kk++) {
            float av[4], bv[4];
#pragma unroll
            for (int i = 0; i < 4; i++) av[i] = As[kk][ty * 4 + i];
#pragma unroll
            for (int j = 0; j < 4; j++) bv[j] = Bs[kk][tx * 4 + j];
#pragma unroll
            for (int i = 0; i < 4; i++)
#pragma unroll
                for (int j = 0; j < 4; j++)
                    acc[i][j] += av[i] * bv[j];
        }
        __syncthreads();
    }
#pragma unroll
    for (int i = 0; i < 4; i++) {
        int gm = bm0 + ty * 4 + i;
        if (gm >= Mr) continue;
#pragma unroll
        for (int j = 0; j < 4; j++) {
            int gn = bn0 + tx * 4 + j;
            if (gn >= Nr) continue;
            float v = acc[i][j];
            if (act == 1) v = v / (1.0f + expf(-v));             // silu
            if (gate) {
                float gl = gate[(size_t)gm * Nr + gn];
                v *= 1.0f / (1.0f + expf(-gl));                  // sigmoid gate
            }
            C[(size_t)gm * Nr + gn] = v;
        }
    }
}

// ---------------- copy initial state into output regions ----------------
__global__ void init_kernel(const float* __restrict__ Ki, const float* __restrict__ Vi,
                            const float* __restrict__ zKi, const float* __restrict__ zVi,
                            float* __restrict__ oK, float* __restrict__ oV,
                            float* __restrict__ ozK, float* __restrict__ ozV)
{
    int i = blockIdx.x * blockDim.x + threadIdx.x;
    const int n = BB * MM * DD;
    if (i < n) { oK[i] = Ki[i]; oV[i] = Vi[i]; }
    if (i < BB * MM) { ozK[i] = zKi[i]; ozV[i] = zVi[i]; }
}

// ---------------- kron addressing: softmax over 2x16, outer product, top-8 ----------------
// one block per bt; warp0 = write addressing (g_zw), warp1 = read addressing (g_zr)
__global__ void addr_kernel(const float* __restrict__ ltw, const float* __restrict__ ltr)
{
    int bt   = blockIdx.x;
    int warp = threadIdx.x >> 5;
    int lane = threadIdx.x & 31;
    const float* z = (warp == 0 ? g_zw : g_zr) + bt * DKK;
    float tau = expf((warp == 0 ? ltw : ltr)[0]);

    float x0 = (lane < 16) ? z[lane]      / tau : -FLT_MAX;
    float x1 = (lane < 16) ? z[16 + lane] / tau : -FLT_MAX;
    float m0 = x0, m1 = x1;
#pragma unroll
    for (int o = 16; o > 0; o >>= 1) {
        m0 = fmaxf(m0, __shfl_xor_sync(0xffffffffu, m0, o));
        m1 = fmaxf(m1, __shfl_xor_sync(0xffffffffu, m1, o));
    }
    float e0 = (lane < 16) ? expf(x0 - m0) : 0.f;
    float e1 = (lane < 16) ? expf(x1 - m1) : 0.f;
    float s0 = e0, s1 = e1;
#pragma unroll
    for (int o = 16; o > 0; o >>= 1) {
        s0 += __shfl_xor_sync(0xffffffffu, s0, o);
        s1 += __shfl_xor_sync(0xffffffffu, s1, o);
    }
    float p0 = e0 / s0, p1 = e1 / s1;

    // addr[i*16 + j] = p0[i] * p1[j]; lane owns indices lane*8 .. lane*8+7
    float av[8];
#pragma unroll
    for (int q = 0; q < 8; q++) {
        int idx = lane * 8 + q;
        float pi = __shfl_sync(0xffffffffu, p0, idx >> 4);
        float pj = __shfl_sync(0xffffffffu, p1, idx & 15);
        av[q] = pi * pj;
    }
    // top-8 by iterative argmax; ties -> smallest index (matches jax.lax.top_k)
    for (int k = 0; k < 8; k++) {
        float bv = -1.f; int bi = 1 << 30;
#pragma unroll
        for (int q = 0; q < 8; q++) {
            if (av[q] > bv) { bv = av[q]; bi = lane * 8 + q; }   // ascending scan: ties keep earliest
        }
#pragma unroll
        for (int o = 16; o > 0; o >>= 1) {
            float ov = __shfl_xor_sync(0xffffffffu, bv, o);
            int   oi = __shfl_xor_sync(0xffffffffu, bi, o);
            if (ov > bv || (ov == bv && oi < bi)) { bv = ov; bi = oi; }
        }
        if (lane == 0) {
            if (warp == 0) { g_widx[bt * 8 + k] = bi; g_ww[bt * 8 + k] = bv; }
            else           { g_ridx[bt * 8 + k] = bi; }
        }
        if ((bi >> 3) == lane) av[bi & 7] = -2.f;   // remove winner
    }
}

// ---------------- k_hat = k_j / max(||k_j||, 1e-12) ----------------
__global__ void norm_kernel()
{
    int row = blockIdx.x;              // bt*NHH + j
    int tid = threadIdx.x;             // 128 threads
    const float* src = g_kj + (size_t)row * DD;
    float s = 0.f;
    for (int i = tid; i < DD; i += 128) { float v = src[i]; s += v * v; }
#pragma unroll
    for (int o = 16; o > 0; o >>= 1) s += __shfl_xor_sync(0xffffffffu, s, o);
    __shared__ float sh[4];
    if ((tid & 31) == 0) sh[tid >> 5] = s;
    __syncthreads();
    float tot = sh[0] + sh[1] + sh[2] + sh[3];
    float inv = 1.0f / fmaxf(sqrtf(tot), 1e-12f);
    for (int i = tid; i < DD; i += 128)
        g_khat[(size_t)row * DD + i] = src[i] * inv;
}

// ---------------- beta = 2*sigmoid(h . hh_bw[j] + hh_bb[j]) ----------------
__global__ void beta_kernel(const float* __restrict__ h, const float* __restrict__ bw,
                            const float* __restrict__ bb)
{
    int gw   = (blockIdx.x * blockDim.x + threadIdx.x) >> 5;
    int lane = threadIdx.x & 31;
    if (gw >= BT * NHH) return;
    int j = gw & 1, bt = gw >> 1;
    const float* hp = h  + (size_t)bt * DD;
    const float* wp = bw + (size_t)j  * DD;
    float s = 0.f;
    for (int i = lane; i < DD; i += 32) s += hp[i] * wp[i];
#pragma unroll
    for (int o = 16; o > 0; o >>= 1) s += __shfl_xor_sync(0xffffffffu, s, o);
    if (lane == 0) g_beta[bt * NHH + j] = 2.0f / (1.0f + expf(-(s + bb[j])));
}

// ---------------- sequential scan: 1 CTA per batch, 16 warps ----------------
__global__ void __launch_bounds__(512) seq_kernel(
    const float* __restrict__ h,
    float* __restrict__ Ks, float* __restrict__ Vs,
    float* __restrict__ zK, float* __restrict__ zV,
    const float* __restrict__ gammap)
{
    int b    = blockIdx.x;
    int tid  = threadIdx.x;
    int warp = tid >> 5, lane = tid & 31;
    int r    = warp & 7;
    bool isV = warp >= 8;
    float sp_gamma = log1pf(expf(gammap[0]));
    const float scale = 1.0f / sqrtf((float)DD);

    __shared__ int   s_widx[8], s_ridx[8];
    __shared__ float s_ww[8], s_beta[2];
    __shared__ float s_rel[8], s_attn[8];
    __shared__ __align__(16) float s_Vn[8][DD];

    float4* KsB = (float4*)(Ks + (size_t)b * MM * DD);
    float4* VsB = (float4*)(Vs + (size_t)b * MM * DD);
    float*  zKb = zK + b * MM;
    float*  zVb = zV + b * MM;

    for (int t = 0; t < TT; t++) {
        int bt = b * TT + t;
        if (tid < 8) {
            s_widx[tid] = g_widx[bt * TOPK + tid];
            s_ww[tid]   = g_ww  [bt * TOPK + tid];
            s_ridx[tid] = g_ridx[bt * TOPK + tid];
        }
        if (tid < 2) s_beta[tid] = g_beta[bt * NHH + tid];
        __syncthreads();

        // ---- write phase: decay + delta-rule on the 8 written slots (K and V) ----
        {
            int   slot  = s_widx[r];
            float w     = s_ww[r];
            float decay = powf(1.0f - w, sp_gamma);
            float4* base = (isV ? VsB : KsB) + slot * (DD / 4);
            float4 row[4];
#pragma unroll
            for (int i = 0; i < 4; i++) {
                float4 v = base[lane + 32 * i];
                row[i] = make_float4(v.x * decay, v.y * decay, v.z * decay, v.w * decay);
            }
            if (warp == 0 && lane < 8) {        // z updates (only written slots change)
                int sl = s_widx[lane]; float wl = s_ww[lane];
                float dl = powf(1.0f - wl, sp_gamma);
                zKb[sl] = dl * zKb[sl] + wl;
                zVb[sl] = dl * zVb[sl] + wl;
            }
            const float4* KH = (const float4*)(g_khat + (size_t)bt * NHH * DD);
            const float4* KJ = (const float4*)(g_kj   + (size_t)bt * NHH * DD);
            const float4* VX = (const float4*)((isV ? g_vv : g_vk) + (size_t)bt * NHH * DD);
#pragma unroll
            for (int j = 0; j < NHH; j++) {
                float be = s_beta[j];
                float4 kh[4];
                float part = 0.f;
#pragma unroll
                for (int i = 0; i < 4; i++) {
                    kh[i] = KH[j * (DD / 4) + lane + 32 * i];
                    part += kh[i].x * row[i].x + kh[i].y * row[i].y
                          + kh[i].z * row[i].z + kh[i].w * row[i].w;
                }
#pragma unroll
                for (int o = 16; o > 0; o >>= 1) part += __shfl_xor_sync(0xffffffffu, part, o);
                float bs = be * part;
#pragma unroll
                for (int i = 0; i < 4; i++) {
                    float4 kj4 = KJ[j * (DD / 4) + lane + 32 * i];
                    float4 vx4 = VX[j * (DD / 4) + lane + 32 * i];
                    row[i].x += be * kj4.x * vx4.x - bs * kh[i].x;
                    row[i].y += be * kj4.y * vx4.y - bs * kh[i].y;
                    row[i].z += be * kj4.z * vx4.z - bs * kh[i].z;
                    row[i].w += be * kj4.w * vx4.w - bs * kh[i].w;
                }
            }
#pragma unroll
            for (int i = 0; i < 4; i++) base[lane + 32 * i] = row[i];
        }
        __syncthreads();

        // ---- read phase: rel dots (K warps) + normalized V rows to smem (V warps) ----
        {
            int slot = s_ridx[r];
            if (!isV) {
                const float4* base = KsB + slot * (DD / 4);
                const float4* H4   = (const float4*)(h + (size_t)bt * DD);
                float part = 0.f;
#pragma unroll
                for (int i = 0; i < 4; i++) {
                    float4 k4 = base[lane + 32 * i];
                    float4 h4 = H4[lane + 32 * i];
                    part += k4.x * h4.x + k4.y * h4.y + k4.z * h4.z + k4.w * h4.w;
                }
#pragma unroll
                for (int o = 16; o > 0; o >>= 1) part += __shfl_xor_sync(0xffffffffu, part, o);
                if (lane == 0) s_rel[r] = part / zKb[slot];
            } else {
                const float4* base = VsB + slot * (DD / 4);
                float invz = 1.0f / zVb[slot];
                float4* dst = (float4*)s_Vn[r];
#pragma unroll
                for (int i = 0; i < 4; i++) {
                    float4 v = base[lane + 32 * i];
                    dst[lane + 32 * i] = make_float4(v.x * invz, v.y * invz, v.z * invz, v.w * invz);
                }
            }
        }
        __syncthreads();

        // ---- softmax over 8 rel values (warp 0) ----
        if (warp == 0) {
            float v = (lane < 8) ? s_rel[lane] * scale : -FLT_MAX;
            float m = v;
#pragma unroll
            for (int o = 16; o > 0; o >>= 1) m = fmaxf(m, __shfl_xor_sync(0xffffffffu, m, o));
            float e = (lane < 8) ? expf(v - m) : 0.f;
            float ssum = e;
#pragma unroll
            for (int o = 16; o > 0; o >>= 1) ssum += __shfl_xor_sync(0xffffffffu, ssum, o);
            if (lane < 8) s_attn[lane] = e / ssum;
        }
        __syncthreads();

        // ---- readout ----
        {
            float acc = 0.f;
#pragma unroll
            for (int i = 0; i < 8; i++) acc += s_attn[i] * s_Vn[i][tid];
            g_RO[(size_t)bt * DD + tid] = acc;
        }
        __syncthreads();
    }
}

// ---------------- final index outputs (as float values) ----------------
__global__ void idxout_kernel(float* __restrict__ ow, float* __restrict__ orr)
{
    int k = threadIdx.x;           // 64 threads
    if (k < BB * TOPK) {
        int b = k >> 3, q = k & 7;
        ow [k] = (float)g_widx[(b * TT + TT - 1) * TOPK + q];
        orr[k] = (float)g_ridx[(b * TT + TT - 1) * TOPK + q];
    }
}

// ---------------- launch ----------------
extern "C" void kernel_launch(void* const* d_in, const int* in_sizes, int n_in,
                              void* d_out, int out_size)
{
    const float* h      = (const float*)d_in[0];
    const float* Kslots = (const float*)d_in[1];
    const float* Vslots = (const float*)d_in[2];
    const float* zKin   = (const float*)d_in[3];
    const float* zVin   = (const float*)d_in[4];
    const float* W_k    = (const float*)d_in[5];
    const float* W_q    = (const float*)d_in[6];
    const float* ltw    = (const float*)d_in[7];
    const float* ltr    = (const float*)d_in[8];
    const float* hh_k   = (const float*)d_in[9];
    const float* hh_vk  = (const float*)d_in[10];
    const float* hh_vv  = (const float*)d_in[11];
    const float* hh_bw  = (const float*)d_in[12];
    const float* hh_bb  = (const float*)d_in[13];
    const float* gamma  = (const float*)d_in[14];
    const float* W_out  = (const float*)d_in[15];
    const float* W_gate = (const float*)d_in[16];

    float* out    = (float*)d_out;
    float* o_outs = out;
    float* o_K    = o_outs + (size_t)BB * TT * DD;
    float* o_V    = o_K    + (size_t)BB * MM * DD;
    float* o_zK   = o_V    + (size_t)BB * MM * DD;
    float* o_zV   = o_zK   + BB * MM;
    float* o_wi   = o_zV   + BB * MM;
    float* o_ri   = o_wi   + BB * TOPK;

    static float* p_zw = nullptr; static float* p_zr = nullptr;
    static float* p_kj = nullptr; static float* p_vk = nullptr;
    static float* p_vv = nullptr; static float* p_gate = nullptr;
    static float* p_RO = nullptr;
    if (!p_zw) {
        cudaGetSymbolAddress((void**)&p_zw,   g_zw);
        cudaGetSymbolAddress((void**)&p_zr,   g_zr);
        cudaGetSymbolAddress((void**)&p_kj,   g_kj);
        cudaGetSymbolAddress((void**)&p_vk,   g_vk);
        cudaGetSymbolAddress((void**)&p_vv,   g_vv);
        cudaGetSymbolAddress((void**)&p_gate, g_gate);
        cudaGetSymbolAddress((void**)&p_RO,   g_RO);
    }

    init_kernel<<<(BB * MM * DD + 255) / 256, 256>>>(Kslots, Vslots, zKin, zVin,
                                                     o_K, o_V, o_zK, o_zV);

    auto gemm = [&](const float* A, const float* Bm, float* C, int Mr, int Nr,
                    int act, const float* gate) {
        dim3 grid((Nr + 63) / 64, (Mr + 63) / 64);
        gemm_kernel<<<grid, 256>>>(A, Bm, C, Mr, Nr, DD, act, gate);
    };

    gemm(h, W_k,    p_zw,   BT, DKK,      0, nullptr);
    gemm(h, W_q,    p_zr,   BT, DKK,      0, nullptr);
    addr_kernel<<<BT, 64>>>(ltw, ltr);
    gemm(h, hh_k,   p_kj,   BT, NHH * DD, 1, nullptr);   // silu epilogue
    gemm(h, hh_vk,  p_vk,   BT, NHH * DD, 0, nullptr);
    gemm(h, hh_vv,  p_vv,   BT, NHH * DD, 0, nullptr);
    gemm(h, W_gate, p_gate, BT, DD,       0, nullptr);
    norm_kernel<<<BT * NHH, 128>>>();
    beta_kernel<<<(BT * NHH * 32 + 255) / 256, 256>>>(h, hh_bw, hh_bb);

    seq_kernel<<<BB, 512>>>(h, o_K, o_V, o_zK, o_zV, gamma);

    gemm(p_RO, W_out, o_outs, BT, DD, 0, p_gate);        // sigmoid-gated output GEMM
    idxout_kernel<<<1, 64>>>(o_wi, o_ri);
}

// round 3
// speedup vs baseline: 1.3299x; 1.3299x over previous
#include <cuda_runtime.h>
#include <math.h>
#include <float.h>

// Problem constants
#define BB   8
#define TT   128
#define DD   512
#define MM   256
#define TOPK 8
#define NHH  2
#define BT   (BB*TT)   // 1024

// ---------------- scratch (static device arrays; no runtime alloc) ----------------
__device__ __align__(16) float g_kj  [BT*NHH*DD];   // silu(h @ hh_k^T)
__device__ __align__(16) float g_khat[BT*NHH*DD];   // normalized
__device__ __align__(16) float g_vk  [BT*NHH*DD];
__device__ __align__(16) float g_vv  [BT*NHH*DD];
__device__ __align__(16) float g_beta[BT*NHH];
__device__ __align__(16) float g_gate[BT*DD];       // gate logits
__device__ __align__(16) float g_RO  [BT*DD];       // attention readout
__device__           int   g_widx[BT*TOPK];
__device__ __align__(16) float g_ww  [BT*TOPK];
__device__           int   g_ridx[BT*TOPK];

// ---------------- init: copy initial state into output regions ----------------
__global__ void init_kernel(const float* __restrict__ Ki, const float* __restrict__ Vi,
                            const float* __restrict__ zKi, const float* __restrict__ zVi,
                            float* __restrict__ oK, float* __restrict__ oV,
                            float* __restrict__ ozK, float* __restrict__ ozV)
{
    int i = blockIdx.x * blockDim.x + threadIdx.x;
    const int n = BB * MM * DD;
    if (i < n) { oK[i] = Ki[i]; oV[i] = Vi[i]; }
    if (i < BB * MM) { ozK[i] = zKi[i]; ozV[i] = zVi[i]; }
}

// ---------------- fused addressing: z = h@W^T (32 dims), kron softmax, top-8 ----------------
// grid = BT, block = 64. warp0: write path (W_k, ltw). warp1: read path (W_q, ltr).
__global__ __launch_bounds__(64) void addr_kernel(
    const float* __restrict__ h,
    const float* __restrict__ W_k, const float* __restrict__ W_q,
    const float* __restrict__ ltw, const float* __restrict__ ltr)
{
    int bt   = blockIdx.x;
    int warp = threadIdx.x >> 5;
    int lane = threadIdx.x & 31;
    const float* W = (warp == 0) ? W_k : W_q;
    float tau = expf((warp == 0 ? ltw : ltr)[0]);

    const float4* h4 = (const float4*)(h + (size_t)bt * DD);
    float4 hreg[4];
#pragma unroll
    for (int i = 0; i < 4; i++) hreg[i] = h4[lane + 32 * i];

    float myz = 0.f;   // lane d holds z[d]
#pragma unroll 4
    for (int d = 0; d < 32; d++) {
        const float4* w4 = (const float4*)(W + (size_t)d * DD);
        float p = 0.f;
#pragma unroll
        for (int i = 0; i < 4; i++) {
            float4 w = w4[lane + 32 * i];
            p += hreg[i].x * w.x + hreg[i].y * w.y + hreg[i].z * w.z + hreg[i].w * w.w;
        }
#pragma unroll
        for (int o = 16; o > 0; o >>= 1) p += __shfl_xor_sync(0xffffffffu, p, o);
        if (lane == d) myz = p;
    }

    float zhi = __shfl_sync(0xffffffffu, myz, (lane + 16) & 31);  // z[lane+16] for lane<16
    float x0 = (lane < 16) ? myz / tau : -FLT_MAX;
    float x1 = (lane < 16) ? zhi / tau : -FLT_MAX;
    float m0 = x0, m1 = x1;
#pragma unroll
    for (int o = 16; o > 0; o >>= 1) {
        m0 = fmaxf(m0, __shfl_xor_sync(0xffffffffu, m0, o));
        m1 = fmaxf(m1, __shfl_xor_sync(0xffffffffu, m1, o));
    }
    float e0 = (lane < 16) ? expf(x0 - m0) : 0.f;
    float e1 = (lane < 16) ? expf(x1 - m1) : 0.f;
    float s0 = e0, s1 = e1;
#pragma unroll
    for (int o = 16; o > 0; o >>= 1) {
        s0 += __shfl_xor_sync(0xffffffffu, s0, o);
        s1 += __shfl_xor_sync(0xffffffffu, s1, o);
    }
    float p0 = e0 / s0, p1 = e1 / s1;

    // addr[i*16+j] = p0[i]*p1[j]; lane owns flat indices lane*8 .. lane*8+7
    float av[8];
#pragma unroll
    for (int q = 0; q < 8; q++) {
        int idx = lane * 8 + q;
        float pi = __shfl_sync(0xffffffffu, p0, idx >> 4);
        float pj = __shfl_sync(0xffffffffu, p1, idx & 15);
        av[q] = pi * pj;
    }
    for (int k = 0; k < 8; k++) {
        float bv = -1.f; int bi = 1 << 30;
#pragma unroll
        for (int q = 0; q < 8; q++)
            if (av[q] > bv) { bv = av[q]; bi = lane * 8 + q; }
#pragma unroll
        for (int o = 16; o > 0; o >>= 1) {
            float ov = __shfl_xor_sync(0xffffffffu, bv, o);
            int   oi = __shfl_xor_sync(0xffffffffu, bi, o);
            if (ov > bv || (ov == bv && oi < bi)) { bv = ov; bi = oi; }
        }
        if (lane == 0) {
            if (warp == 0) { g_widx[bt * 8 + k] = bi; g_ww[bt * 8 + k] = bv; }
            else           { g_ridx[bt * 8 + k] = bi; }
        }
        if ((bi >> 3) == lane) av[bi & 7] = -2.f;
    }
}

// ---------------- mega GEMM: C = h @ B^T for {hh_k(silu), hh_vk, hh_vv, W_gate} ----------------
// 128x128 tiles, BK=16, 256 threads, 8x8 per-thread, register prefetch pipeline.
// grid = (28, 8): 24 tiles for the three 1024-col matrices + 4 for gate.
__global__ __launch_bounds__(256) void mega_gemm(
    const float* __restrict__ h,
    const float* __restrict__ hh_k, const float* __restrict__ hh_vk,
    const float* __restrict__ hh_vv, const float* __restrict__ W_gate)
{
    int nt = blockIdx.x, mt = blockIdx.y;
    const float* Bb; float* Cd; int ldc, ncol0, act = 0;
    if (nt < 8)       { Bb = hh_k   + (size_t)nt        * 128 * DD; Cd = g_kj;   ldc = NHH * DD; ncol0 = nt        * 128; act = 1; }
    else if (nt < 16) { Bb = hh_vk  + (size_t)(nt - 8)  * 128 * DD; Cd = g_vk;   ldc = NHH * DD; ncol0 = (nt - 8)  * 128; }
    else if (nt < 24) { Bb = hh_vv  + (size_t)(nt - 16) * 128 * DD; Cd = g_vv;   ldc = NHH * DD; ncol0 = (nt - 16) * 128; }
    else              { Bb = W_gate + (size_t)(nt - 24) * 128 * DD; Cd = g_gate; ldc = DD;       ncol0 = (nt - 24) * 128; }
    const float* Ab = h + (size_t)mt * 128 * DD;

    __shared__ float As[16][132];
    __shared__ float Bs[16][132];
    int tid = threadIdx.x;
    int tx = tid & 15, ty = tid >> 4;
    int lr = tid >> 2;            // 0..63
    int lc = (tid & 3) * 4;       // 0,4,8,12

    float acc[8][8];
#pragma unroll
    for (int i = 0; i < 8; i++)
#pragma unroll
        for (int j = 0; j < 8; j++) acc[i][j] = 0.f;

    float4 pa0 = *(const float4*)(Ab + (size_t)lr        * DD + lc);
    float4 pa1 = *(const float4*)(Ab + (size_t)(lr + 64) * DD + lc);
    float4 pb0 = *(const float4*)(Bb + (size_t)lr        * DD + lc);
    float4 pb1 = *(const float4*)(Bb + (size_t)(lr + 64) * DD + lc);

    for (int k0 = 0; k0 < DD; k0 += 16) {
        As[lc + 0][lr]      = pa0.x; As[lc + 1][lr]      = pa0.y; As[lc + 2][lr]      = pa0.z; As[lc + 3][lr]      = pa0.w;
        As[lc + 0][lr + 64] = pa1.x; As[lc + 1][lr + 64] = pa1.y; As[lc + 2][lr + 64] = pa1.z; As[lc + 3][lr + 64] = pa1.w;
        Bs[lc + 0][lr]      = pb0.x; Bs[lc + 1][lr]      = pb0.y; Bs[lc + 2][lr]      = pb0.z; Bs[lc + 3][lr]      = pb0.w;
        Bs[lc + 0][lr + 64] = pb1.x; Bs[lc + 1][lr + 64] = pb1.y; Bs[lc + 2][lr + 64] = pb1.z; Bs[lc + 3][lr + 64] = pb1.w;
        __syncthreads();
        if (k0 + 16 < DD) {
            int kn = k0 + 16;
            pa0 = *(const float4*)(Ab + (size_t)lr        * DD + kn + lc);
            pa1 = *(const float4*)(Ab + (size_t)(lr + 64) * DD + kn + lc);
            pb0 = *(const float4*)(Bb + (size_t)lr        * DD + kn + lc);
            pb1 = *(const float4*)(Bb + (size_t)(lr + 64) * DD + kn + lc);
        }
#pragma unroll
        for (int kk = 0; kk < 16; kk++) {
            float4 a0 = *(const float4*)&As[kk][ty * 8];
            float4 a1 = *(const float4*)&As[kk][ty * 8 + 4];
            float4 b0 = *(const float4*)&Bs[kk][tx * 8];
            float4 b1 = *(const float4*)&Bs[kk][tx * 8 + 4];
            float avv[8] = {a0.x, a0.y, a0.z, a0.w, a1.x, a1.y, a1.z, a1.w};
            float bvv[8] = {b0.x, b0.y, b0.z, b0.w, b1.x, b1.y, b1.z, b1.w};
#pragma unroll
            for (int i = 0; i < 8; i++)
#pragma unroll
                for (int j = 0; j < 8; j++)
                    acc[i][j] += avv[i] * bvv[j];
        }
        __syncthreads();
    }

#pragma unroll
    for (int i = 0; i < 8; i++) {
        int row = mt * 128 + ty * 8 + i;
        float* crow = Cd + (size_t)row * ldc + ncol0 + tx * 8;
        float v[8];
#pragma unroll
        for (int j = 0; j < 8; j++) {
            v[j] = acc[i][j];
            if (act) v[j] = v[j] / (1.0f + expf(-v[j]));
        }
        *(float4*)&crow[0] = make_float4(v[0], v[1], v[2], v[3]);
        *(float4*)&crow[4] = make_float4(v[4], v[5], v[6], v[7]);
    }
}

// ---------------- final gated GEMM: out = sigmoid(gate) * (RO @ W_out^T), 64x64 tiles ----------------
// grid = (8, 16), 256 threads, 4x4 per thread.
__global__ __launch_bounds__(256) void out_gemm(const float* __restrict__ W_out,
                                                float* __restrict__ C)
{
    int nt = blockIdx.x, mt = blockIdx.y;
    const float* Ab = g_RO + (size_t)mt * 64 * DD;
    const float* Bb = W_out + (size_t)nt * 64 * DD;

    __shared__ float As[16][68];
    __shared__ float Bs[16][68];
    int tid = threadIdx.x;
    int tx = tid & 15, ty = tid >> 4;
    int lr = tid >> 2;            // 0..63
    int lc = (tid & 3) * 4;

    float acc[4][4];
#pragma unroll
    for (int i = 0; i < 4; i++)
#pragma unroll
        for (int j = 0; j < 4; j++) acc[i][j] = 0.f;

    float4 pa = *(const float4*)(Ab + (size_t)lr * DD + lc);
    float4 pb = *(const float4*)(Bb + (size_t)lr * DD + lc);

    for (int k0 = 0; k0 < DD; k0 += 16) {
        As[lc + 0][lr] = pa.x; As[lc + 1][lr] = pa.y; As[lc + 2][lr] = pa.z; As[lc + 3][lr] = pa.w;
        Bs[lc + 0][lr] = pb.x; Bs[lc + 1][lr] = pb.y; Bs[lc + 2][lr] = pb.z; Bs[lc + 3][lr] = pb.w;
        __syncthreads();
        if (k0 + 16 < DD) {
            int kn = k0 + 16;
            pa = *(const float4*)(Ab + (size_t)lr * DD + kn + lc);
            pb = *(const float4*)(Bb + (size_t)lr * DD + kn + lc);
        }
#pragma unroll
        for (int kk = 0; kk < 16; kk++) {
            float4 a0 = *(const float4*)&As[kk][ty * 4];
            float4 b0 = *(const float4*)&Bs[kk][tx * 4];
            float avv[4] = {a0.x, a0.y, a0.z, a0.w};
            float bvv[4] = {b0.x, b0.y, b0.z, b0.w};
#pragma unroll
            for (int i = 0; i < 4; i++)
#pragma unroll
                for (int j = 0; j < 4; j++)
                    acc[i][j] += avv[i] * bvv[j];
        }
        __syncthreads();
    }

#pragma unroll
    for (int i = 0; i < 4; i++) {
        int row = mt * 64 + ty * 4 + i;
        int col0 = nt * 64 + tx * 4;
        const float* grow = g_gate + (size_t)row * DD + col0;
        float* crow = C + (size_t)row * DD + col0;
        float v[4];
#pragma unroll
        for (int j = 0; j < 4; j++)
            v[j] = acc[i][j] * (1.0f / (1.0f + expf(-grow[j])));
        *(float4*)crow = make_float4(v[0], v[1], v[2], v[3]);
    }
}

// ---------------- k_hat = k_j / max(||k_j||, 1e-12) ----------------
__global__ void norm_kernel()
{
    int row = blockIdx.x;              // bt*NHH + j
    int tid = threadIdx.x;             // 128 threads
    const float* src = g_kj + (size_t)row * DD;
    float s = 0.f;
    for (int i = tid; i < DD; i += 128) { float v = src[i]; s += v * v; }
#pragma unroll
    for (int o = 16; o > 0; o >>= 1) s += __shfl_xor_sync(0xffffffffu, s, o);
    __shared__ float sh[4];
    if ((tid & 31) == 0) sh[tid >> 5] = s;
    __syncthreads();
    float tot = sh[0] + sh[1] + sh[2] + sh[3];
    float inv = 1.0f / fmaxf(sqrtf(tot), 1e-12f);
    for (int i = tid; i < DD; i += 128)
        g_khat[(size_t)row * DD + i] = src[i] * inv;
}

// ---------------- beta = 2*sigmoid(h . hh_bw[j] + hh_bb[j]) ----------------
__global__ void beta_kernel(const float* __restrict__ h, const float* __restrict__ bw,
                            const float* __restrict__ bb)
{
    int gw   = (blockIdx.x * blockDim.x + threadIdx.x) >> 5;
    int lane = threadIdx.x & 31;
    if (gw >= BT * NHH) return;
    int j = gw & 1, bt = gw >> 1;
    const float* hp = h  + (size_t)bt * DD;
    const float* wp = bw + (size_t)j  * DD;
    float s = 0.f;
    for (int i = lane; i < DD; i += 32) s += hp[i] * wp[i];
#pragma unroll
    for (int o = 16; o > 0; o >>= 1) s += __shfl_xor_sync(0xffffffffu, s, o);
    if (lane == 0) g_beta[bt * NHH + j] = 2.0f / (1.0f + expf(-(s + bb[j])));
}

// ---------------- sequential scan: 1 CTA per batch, 16 warps, 3 syncs/step ----------------
__global__ void __launch_bounds__(512) seq_kernel(
    const float* __restrict__ h,
    float* __restrict__ Ks, float* __restrict__ Vs,
    float* __restrict__ zK, float* __restrict__ zV,
    const float* __restrict__ gammap)
{
    int b    = blockIdx.x;
    int tid  = threadIdx.x;
    int warp = tid >> 5, lane = tid & 31;
    int r    = warp & 7;
    bool isV = warp >= 8;
    float sp_gamma = log1pf(expf(gammap[0]));
    const float scale = 1.0f / sqrtf((float)DD);

    __shared__ int   s_widx[2][8], s_ridx[2][8];
    __shared__ float s_ww[2][8], s_beta[2][2];
    __shared__ float s_rel[8], s_attn[8];
    __shared__ float s_zK[MM], s_zV[MM];
    __shared__ __align__(16) float s_Vn[8][DD];

    float4* KsB = (float4*)(Ks + (size_t)b * MM * DD);
    float4* VsB = (float4*)(Vs + (size_t)b * MM * DD);
    float*  zKb = zK + b * MM;
    float*  zVb = zV + b * MM;

    // load z into smem; preload step-0 indices
    for (int i = tid; i < MM; i += 512) { s_zK[i] = zKb[i]; s_zV[i] = zVb[i]; }
    {
        int bt0 = b * TT;
        if (tid < 8) {
            s_widx[0][tid] = g_widx[bt0 * TOPK + tid];
            s_ww  [0][tid] = g_ww  [bt0 * TOPK + tid];
            s_ridx[0][tid] = g_ridx[bt0 * TOPK + tid];
        }
        if (tid < 2) s_beta[0][tid] = g_beta[bt0 * NHH + tid];
    }
    __syncthreads();

    for (int t = 0; t < TT; t++) {
        int bt = b * TT + t;
        int pb = t & 1;

        // ---- write phase: decay + delta-rule on the 8 written slots ----
        {
            int   slot  = s_widx[pb][r];
            float w     = s_ww[pb][r];
            float decay = powf(1.0f - w, sp_gamma);
            float4* base = (isV ? VsB : KsB) + slot * (DD / 4);
            float4 row[4];
#pragma unroll
            for (int i = 0; i < 4; i++) {
                float4 v = base[lane + 32 * i];
                row[i] = make_float4(v.x * decay, v.y * decay, v.z * decay, v.w * decay);
            }
            if (warp == 0 && lane < 8) {   // z updates (smem)
                int sl = s_widx[pb][lane]; float wl = s_ww[pb][lane];
                float dl = powf(1.0f - wl, sp_gamma);
                s_zK[sl] = dl * s_zK[sl] + wl;
                s_zV[sl] = dl * s_zV[sl] + wl;
            }
            const float4* KH = (const float4*)(g_khat + (size_t)bt * NHH * DD);
            const float4* KJ = (const float4*)(g_kj   + (size_t)bt * NHH * DD);
            const float4* VX = (const float4*)((isV ? g_vv : g_vk) + (size_t)bt * NHH * DD);
#pragma unroll
            for (int j = 0; j < NHH; j++) {
                float be = s_beta[pb][j];
                float4 kh[4];
                float part = 0.f;
#pragma unroll
                for (int i = 0; i < 4; i++) {
                    kh[i] = KH[j * (DD / 4) + lane + 32 * i];
                    part += kh[i].x * row[i].x + kh[i].y * row[i].y
                          + kh[i].z * row[i].z + kh[i].w * row[i].w;
                }
#pragma unroll
                for (int o = 16; o > 0; o >>= 1) part += __shfl_xor_sync(0xffffffffu, part, o);
                float bs = be * part;
#pragma unroll
                for (int i = 0; i < 4; i++) {
                    float4 kj4 = KJ[j * (DD / 4) + lane + 32 * i];
                    float4 vx4 = VX[j * (DD / 4) + lane + 32 * i];
                    row[i].x += be * kj4.x * vx4.x - bs * kh[i].x;
                    row[i].y += be * kj4.y * vx4.y - bs * kh[i].y;
                    row[i].z += be * kj4.z * vx4.z - bs * kh[i].z;
                    row[i].w += be * kj4.w * vx4.w - bs * kh[i].w;
                }
            }
#pragma unroll
            for (int i = 0; i < 4; i++) base[lane + 32 * i] = row[i];
        }
        __syncthreads();   // A: state stores + z updates visible

        // ---- read phase ----
        {
            int slot = s_ridx[pb][r];
            if (!isV) {
                const float4* base = KsB + slot * (DD / 4);
                const float4* H4   = (const float4*)(h + (size_t)bt * DD);
                float part = 0.f;
#pragma unroll
                for (int i = 0; i < 4; i++) {
                    float4 k4 = base[lane + 32 * i];
                    float4 h4 = H4[lane + 32 * i];
                    part += k4.x * h4.x + k4.y * h4.y + k4.z * h4.z + k4.w * h4.w;
                }
#pragma unroll
                for (int o = 16; o > 0; o >>= 1) part += __shfl_xor_sync(0xffffffffu, part, o);
                if (lane == 0) s_rel[r] = part / s_zK[slot];
            } else {
                const float4* base = VsB + slot * (DD / 4);
                float invz = 1.0f / s_zV[slot];
                float4* dst = (float4*)s_Vn[r];
#pragma unroll
                for (int i = 0; i < 4; i++) {
                    float4 v = base[lane + 32 * i];
                    dst[lane + 32 * i] = make_float4(v.x * invz, v.y * invz, v.z * invz, v.w * invz);
                }
            }
        }
        __syncthreads();   // B: s_rel + s_Vn visible

        // ---- softmax (warp 0) + next-step index prefetch (warp 1) ----
        if (warp == 0) {
            float v = (lane < 8) ? s_rel[lane] * scale : -FLT_MAX;
            float m = v;
#pragma unroll
            for (int o = 16; o > 0; o >>= 1) m = fmaxf(m, __shfl_xor_sync(0xffffffffu, m, o));
            float e = (lane < 8) ? expf(v - m) : 0.f;
            float ssum = e;
#pragma unroll
            for (int o = 16; o > 0; o >>= 1) ssum += __shfl_xor_sync(0xffffffffu, ssum, o);
            if (lane < 8) s_attn[lane] = e / ssum;
        } else if (warp == 1 && t + 1 < TT) {
            int nbt = bt + 1, nb = (t + 1) & 1;
            if (lane < 8) {
                s_widx[nb][lane] = g_widx[nbt * TOPK + lane];
                s_ww  [nb][lane] = g_ww  [nbt * TOPK + lane];
                s_ridx[nb][lane] = g_ridx[nbt * TOPK + lane];
            }
            if (lane < 2) s_beta[nb][lane] = g_beta[nbt * NHH + lane];
        }
        __syncthreads();   // C: s_attn + next indices visible

        // ---- readout (no trailing sync needed: next write phase touches no smem read here) ----
        {
            float acc = 0.f;
#pragma unroll
            for (int i = 0; i < 8; i++) acc += s_attn[i] * s_Vn[i][tid];
            g_RO[(size_t)bt * DD + tid] = acc;
        }
    }

    __syncthreads();
    for (int i = tid; i < MM; i += 512) { zKb[i] = s_zK[i]; zVb[i] = s_zV[i]; }
}

// ---------------- final index outputs (as float values) ----------------
__global__ void idxout_kernel(float* __restrict__ ow, float* __restrict__ orr)
{
    int k = threadIdx.x;
    if (k < BB * TOPK) {
        int b = k >> 3, q = k & 7;
        ow [k] = (float)g_widx[(b * TT + TT - 1) * TOPK + q];
        orr[k] = (float)g_ridx[(b * TT + TT - 1) * TOPK + q];
    }
}

// ---------------- launch ----------------
extern "C" void kernel_launch(void* const* d_in, const int* in_sizes, int n_in,
                              void* d_out, int out_size)
{
    const float* h      = (const float*)d_in[0];
    const float* Kslots = (const float*)d_in[1];
    const float* Vslots = (const float*)d_in[2];
    const float* zKin   = (const float*)d_in[3];
    const float* zVin   = (const float*)d_in[4];
    const float* W_k    = (const float*)d_in[5];
    const float* W_q    = (const float*)d_in[6];
    const float* ltw    = (const float*)d_in[7];
    const float* ltr    = (const float*)d_in[8];
    const float* hh_k   = (const float*)d_in[9];
    const float* hh_vk  = (const float*)d_in[10];
    const float* hh_vv  = (const float*)d_in[11];
    const float* hh_bw  = (const float*)d_in[12];
    const float* hh_bb  = (const float*)d_in[13];
    const float* gamma  = (const float*)d_in[14];
    const float* W_out  = (const float*)d_in[15];
    const float* W_gate = (const float*)d_in[16];

    float* out    = (float*)d_out;
    float* o_outs = out;
    float* o_K    = o_outs + (size_t)BB * TT * DD;
    float* o_V    = o_K    + (size_t)BB * MM * DD;
    float* o_zK   = o_V    + (size_t)BB * MM * DD;
    float* o_zV   = o_zK   + BB * MM;
    float* o_wi   = o_zV   + BB * MM;
    float* o_ri   = o_wi   + BB * TOPK;

    init_kernel<<<(BB * MM * DD + 255) / 256, 256>>>(Kslots, Vslots, zKin, zVin,
                                                     o_K, o_V, o_zK, o_zV);
    addr_kernel<<<BT, 64>>>(h, W_k, W_q, ltw, ltr);
    mega_gemm<<<dim3(28, 8), 256>>>(h, hh_k, hh_vk, hh_vv, W_gate);
    norm_kernel<<<BT * NHH, 128>>>();
    beta_kernel<<<(BT * NHH * 32 + 255) / 256, 256>>>(h, hh_bw, hh_bb);

    seq_kernel<<<BB, 512>>>(h, o_K, o_V, o_zK, o_zV, gamma);

    out_gemm<<<dim3(8, 16), 256>>>(W_out, o_outs);
    idxout_kernel<<<1, 64>>>(o_wi, o_ri);
}

// round 6
// speedup vs baseline: 1.6768x; 1.2609x over previous
#include <cuda_runtime.h>
#include <math.h>
#include <float.h>

// Problem constants
#define BB   8
#define TT   128
#define DD   512
#define MM   256
#define TOPK 8
#define NHH  2
#define BT   (BB*TT)   // 1024

// ---------------- scratch ----------------
__device__ __align__(16) float g_kj  [BT*NHH*DD];   // silu(h @ hh_k^T) (silu fused in mega_gemm)
__device__ __align__(16) float g_vk  [BT*NHH*DD];
__device__ __align__(16) float g_vv  [BT*NHH*DD];
__device__ __align__(16) float g_beta[BT*NHH];
__device__ __align__(16) float g_kinv[BT*NHH];      // 1/max(||kj||,1e-12)
__device__ __align__(16) float g_gate[BT*DD];       // gate logits
__device__ __align__(16) float g_RO  [BT*DD];       // attention readout
__device__           int   g_widx[BT*TOPK];
__device__ __align__(16) float g_ww  [BT*TOPK];
__device__ __align__(16) float g_dec [BT*TOPK];     // (1-w)^softplus(gamma), precomputed
__device__           int   g_ridx[BT*TOPK];

// ---------------- init ----------------
__global__ void init_kernel(const float* __restrict__ Ki, const float* __restrict__ Vi,
                            const float* __restrict__ zKi, const float* __restrict__ zVi,
                            float* __restrict__ oK, float* __restrict__ oV,
                            float* __restrict__ ozK, float* __restrict__ ozV)
{
    int i = blockIdx.x * blockDim.x + threadIdx.x;
    const int n = BB * MM * DD;
    if (i < n) { oK[i] = Ki[i]; oV[i] = Vi[i]; }
    if (i < BB * MM) { ozK[i] = zKi[i]; ozV[i] = zVi[i]; }
}

// ---------------- fused addressing (exact fp32 — controls integer indices) ----------------
__global__ __launch_bounds__(64) void addr_kernel(
    const float* __restrict__ h,
    const float* __restrict__ W_k, const float* __restrict__ W_q,
    const float* __restrict__ ltw, const float* __restrict__ ltr)
{
    int bt   = blockIdx.x;
    int warp = threadIdx.x >> 5;
    int lane = threadIdx.x & 31;
    const float* W = (warp == 0) ? W_k : W_q;
    float tau = expf((warp == 0 ? ltw : ltr)[0]);

    const float4* h4 = (const float4*)(h + (size_t)bt * DD);
    float4 hreg[4];
#pragma unroll
    for (int i = 0; i < 4; i++) hreg[i] = h4[lane + 32 * i];

    float myz = 0.f;
#pragma unroll 4
    for (int d = 0; d < 32; d++) {
        const float4* w4 = (const float4*)(W + (size_t)d * DD);
        float p = 0.f;
#pragma unroll
        for (int i = 0; i < 4; i++) {
            float4 w = w4[lane + 32 * i];
            p += hreg[i].x * w.x + hreg[i].y * w.y + hreg[i].z * w.z + hreg[i].w * w.w;
        }
#pragma unroll
        for (int o = 16; o > 0; o >>= 1) p += __shfl_xor_sync(0xffffffffu, p, o);
        if (lane == d) myz = p;
    }

    float zhi = __shfl_sync(0xffffffffu, myz, (lane + 16) & 31);
    float x0 = (lane < 16) ? myz / tau : -FLT_MAX;
    float x1 = (lane < 16) ? zhi / tau : -FLT_MAX;
    float m0 = x0, m1 = x1;
#pragma unroll
    for (int o = 16; o > 0; o >>= 1) {
        m0 = fmaxf(m0, __shfl_xor_sync(0xffffffffu, m0, o));
        m1 = fmaxf(m1, __shfl_xor_sync(0xffffffffu, m1, o));
    }
    float e0 = (lane < 16) ? expf(x0 - m0) : 0.f;
    float e1 = (lane < 16) ? expf(x1 - m1) : 0.f;
    float s0 = e0, s1 = e1;
#pragma unroll
    for (int o = 16; o > 0; o >>= 1) {
        s0 += __shfl_xor_sync(0xffffffffu, s0, o);
        s1 += __shfl_xor_sync(0xffffffffu, s1, o);
    }
    float p0 = e0 / s0, p1 = e1 / s1;

    float av[8];
#pragma unroll
    for (int q = 0; q < 8; q++) {
        int idx = lane * 8 + q;
        float pi = __shfl_sync(0xffffffffu, p0, idx >> 4);
        float pj = __shfl_sync(0xffffffffu, p1, idx & 15);
        av[q] = pi * pj;
    }
    for (int k = 0; k < 8; k++) {
        float bv = -1.f; int bi = 1 << 30;
#pragma unroll
        for (int q = 0; q < 8; q++)
            if (av[q] > bv) { bv = av[q]; bi = lane * 8 + q; }
#pragma unroll
        for (int o = 16; o > 0; o >>= 1) {
            float ov = __shfl_xor_sync(0xffffffffu, bv, o);
            int   oi = __shfl_xor_sync(0xffffffffu, bi, o);
            if (ov > bv || (ov == bv && oi < bi)) { bv = ov; bi = oi; }
        }
        if (lane == 0) {
            if (warp == 0) { g_widx[bt * 8 + k] = bi; g_ww[bt * 8 + k] = bv; }
            else           { g_ridx[bt * 8 + k] = bi; }
        }
        if ((bi >> 3) == lane) av[bi & 7] = -2.f;
    }
}

// ---------------- decay precompute ----------------
__global__ void decay_kernel(const float* __restrict__ gammap)
{
    int i = blockIdx.x * blockDim.x + threadIdx.x;
    if (i < BT * TOPK) {
        float g = log1pf(expf(gammap[0]));
        g_dec[i] = powf(1.0f - g_ww[i], g);
    }
}

// ---------------- mega GEMM (FFMA, known-good R3): {hh_k(silu), hh_vk, hh_vv, W_gate} ----------------
__global__ __launch_bounds__(256) void mega_gemm(
    const float* __restrict__ h,
    const float* __restrict__ hh_k, const float* __restrict__ hh_vk,
    const float* __restrict__ hh_vv, const float* __restrict__ W_gate)
{
    int nt = blockIdx.x, mt = blockIdx.y;
    const float* Bb; float* Cd; int ldc, ncol0, act = 0;
    if (nt < 8)       { Bb = hh_k   + (size_t)nt        * 128 * DD; Cd = g_kj;   ldc = NHH * DD; ncol0 = nt        * 128; act = 1; }
    else if (nt < 16) { Bb = hh_vk  + (size_t)(nt - 8)  * 128 * DD; Cd = g_vk;   ldc = NHH * DD; ncol0 = (nt - 8)  * 128; }
    else if (nt < 24) { Bb = hh_vv  + (size_t)(nt - 16) * 128 * DD; Cd = g_vv;   ldc = NHH * DD; ncol0 = (nt - 16) * 128; }
    else              { Bb = W_gate + (size_t)(nt - 24) * 128 * DD; Cd = g_gate; ldc = DD;       ncol0 = (nt - 24) * 128; }
    const float* Ab = h + (size_t)mt * 128 * DD;

    __shared__ float As[16][132];
    __shared__ float Bs[16][132];
    int tid = threadIdx.x;
    int tx = tid & 15, ty = tid >> 4;
    int lr = tid >> 2;            // 0..63
    int lc = (tid & 3) * 4;       // 0,4,8,12

    float acc[8][8];
#pragma unroll
    for (int i = 0; i < 8; i++)
#pragma unroll
        for (int j = 0; j < 8; j++) acc[i][j] = 0.f;

    float4 pa0 = *(const float4*)(Ab + (size_t)lr        * DD + lc);
    float4 pa1 = *(const float4*)(Ab + (size_t)(lr + 64) * DD + lc);
    float4 pb0 = *(const float4*)(Bb + (size_t)lr        * DD + lc);
    float4 pb1 = *(const float4*)(Bb + (size_t)(lr + 64) * DD + lc);

    for (int k0 = 0; k0 < DD; k0 += 16) {
        As[lc + 0][lr]      = pa0.x; As[lc + 1][lr]      = pa0.y; As[lc + 2][lr]      = pa0.z; As[lc + 3][lr]      = pa0.w;
        As[lc + 0][lr + 64] = pa1.x; As[lc + 1][lr + 64] = pa1.y; As[lc + 2][lr + 64] = pa1.z; As[lc + 3][lr + 64] = pa1.w;
        Bs[lc + 0][lr]      = pb0.x; Bs[lc + 1][lr]      = pb0.y; Bs[lc + 2][lr]      = pb0.z; Bs[lc + 3][lr]      = pb0.w;
        Bs[lc + 0][lr + 64] = pb1.x; Bs[lc + 1][lr + 64] = pb1.y; Bs[lc + 2][lr + 64] = pb1.z; Bs[lc + 3][lr + 64] = pb1.w;
        __syncthreads();
        if (k0 + 16 < DD) {
            int kn = k0 + 16;
            pa0 = *(const float4*)(Ab + (size_t)lr        * DD + kn + lc);
            pa1 = *(const float4*)(Ab + (size_t)(lr + 64) * DD + kn + lc);
            pb0 = *(const float4*)(Bb + (size_t)lr        * DD + kn + lc);
            pb1 = *(const float4*)(Bb + (size_t)(lr + 64) * DD + kn + lc);
        }
#pragma unroll
        for (int kk = 0; kk < 16; kk++) {
            float4 a0 = *(const float4*)&As[kk][ty * 8];
            float4 a1 = *(const float4*)&As[kk][ty * 8 + 4];
            float4 b0 = *(const float4*)&Bs[kk][tx * 8];
            float4 b1 = *(const float4*)&Bs[kk][tx * 8 + 4];
            float avv[8] = {a0.x, a0.y, a0.z, a0.w, a1.x, a1.y, a1.z, a1.w};
            float bvv[8] = {b0.x, b0.y, b0.z, b0.w, b1.x, b1.y, b1.z, b1.w};
#pragma unroll
            for (int i = 0; i < 8; i++)
#pragma unroll
                for (int j = 0; j < 8; j++)
                    acc[i][j] += avv[i] * bvv[j];
        }
        __syncthreads();
    }

#pragma unroll
    for (int i = 0; i < 8; i++) {
        int row = mt * 128 + ty * 8 + i;
        float* crow = Cd + (size_t)row * ldc + ncol0 + tx * 8;
        float v[8];
#pragma unroll
        for (int j = 0; j < 8; j++) {
            v[j] = acc[i][j];
            if (act) v[j] = v[j] / (1.0f + expf(-v[j]));
        }
        *(float4*)&crow[0] = make_float4(v[0], v[1], v[2], v[3]);
        *(float4*)&crow[4] = make_float4(v[4], v[5], v[6], v[7]);
    }
}

// ---------------- final gated GEMM (FFMA, known-good R3): grid (8, 16) ----------------
__global__ __launch_bounds__(256) void out_gemm(const float* __restrict__ W_out,
                                                float* __restrict__ C)
{
    int nt = blockIdx.x, mt = blockIdx.y;
    const float* Ab = g_RO + (size_t)mt * 64 * DD;
    const float* Bb = W_out + (size_t)nt * 64 * DD;

    __shared__ float As[16][68];
    __shared__ float Bs[16][68];
    int tid = threadIdx.x;
    int tx = tid & 15, ty = tid >> 4;
    int lr = tid >> 2;
    int lc = (tid & 3) * 4;

    float acc[4][4];
#pragma unroll
    for (int i = 0; i < 4; i++)
#pragma unroll
        for (int j = 0; j < 4; j++) acc[i][j] = 0.f;

    float4 pa = *(const float4*)(Ab + (size_t)lr * DD + lc);
    float4 pb = *(const float4*)(Bb + (size_t)lr * DD + lc);

    for (int k0 = 0; k0 < DD; k0 += 16) {
        As[lc + 0][lr] = pa.x; As[lc + 1][lr] = pa.y; As[lc + 2][lr] = pa.z; As[lc + 3][lr] = pa.w;
        Bs[lc + 0][lr] = pb.x; Bs[lc + 1][lr] = pb.y; Bs[lc + 2][lr] = pb.z; Bs[lc + 3][lr] = pb.w;
        __syncthreads();
        if (k0 + 16 < DD) {
            int kn = k0 + 16;
            pa = *(const float4*)(Ab + (size_t)lr * DD + kn + lc);
            pb = *(const float4*)(Bb + (size_t)lr * DD + kn + lc);
        }
#pragma unroll
        for (int kk = 0; kk < 16; kk++) {
            float4 a0 = *(const float4*)&As[kk][ty * 4];
            float4 b0 = *(const float4*)&Bs[kk][tx * 4];
            float avv[4] = {a0.x, a0.y, a0.z, a0.w};
            float bvv[4] = {b0.x, b0.y, b0.z, b0.w};
#pragma unroll
            for (int i = 0; i < 4; i++)
#pragma unroll
                for (int j = 0; j < 4; j++)
                    acc[i][j] += avv[i] * bvv[j];
        }
        __syncthreads();
    }

#pragma unroll
    for (int i = 0; i < 4; i++) {
        int row = mt * 64 + ty * 4 + i;
        int col0 = nt * 64 + tx * 4;
        const float* grow = g_gate + (size_t)row * DD + col0;
        float* crow = C + (size_t)row * DD + col0;
        float v[4];
#pragma unroll
        for (int j = 0; j < 4; j++)
            v[j] = acc[i][j] * (1.0f / (1.0f + expf(-grow[j])));
        *(float4*)crow = make_float4(v[0], v[1], v[2], v[3]);
    }
}

// ---------------- norm (1/||kj||) + beta, fused. grid = BT*NHH, block = 128 ----------------
__global__ void norm_kernel(const float* __restrict__ h, const float* __restrict__ bw,
                            const float* __restrict__ bb)
{
    int row = blockIdx.x;              // bt*NHH + j
    int tid = threadIdx.x;             // 128 threads
    int bt = row >> 1, j = row & 1;
    const float* src = g_kj + (size_t)row * DD;
    const float* hp  = h   + (size_t)bt  * DD;
    const float* wp  = bw  + (size_t)j   * DD;
    float s = 0.f, bsum = 0.f;
#pragma unroll
    for (int q = 0; q < 4; q++) {
        float v = src[tid + 128 * q];
        s += v * v;
        bsum += hp[tid + 128 * q] * wp[tid + 128 * q];
    }
#pragma unroll
    for (int o = 16; o > 0; o >>= 1) {
        s    += __shfl_xor_sync(0xffffffffu, s, o);
        bsum += __shfl_xor_sync(0xffffffffu, bsum, o);
    }
    __shared__ float sh1[4], sh2[4];
    if ((tid & 31) == 0) { sh1[tid >> 5] = s; sh2[tid >> 5] = bsum; }
    __syncthreads();
    if (tid == 0) {
        float tot = sh1[0] + sh1[1] + sh1[2] + sh1[3];
        float bt2 = sh2[0] + sh2[1] + sh2[2] + sh2[3];
        g_kinv[row] = 1.0f / fmaxf(sqrtf(tot), 1e-12f);
        g_beta[row] = 2.0f / (1.0f + expf(-(bt2 + bb[j])));
    }
}

// ---------------- sequential scan: 1 CTA/batch, 512 threads, smem-staged operands ----------------
__global__ void __launch_bounds__(512) seq_kernel(
    const float* __restrict__ h,
    float* __restrict__ Ks, float* __restrict__ Vs,
    float* __restrict__ zK, float* __restrict__ zV)
{
    int b    = blockIdx.x;
    int tid  = threadIdx.x;
    int warp = tid >> 5, lane = tid & 31;
    int r    = warp & 7;
    bool isV = warp >= 8;
    const float scale = 1.0f / sqrtf((float)DD);

    __shared__ __align__(16) float s_kj[2][NHH*DD];
    __shared__ __align__(16) float s_vk[2][NHH*DD];
    __shared__ __align__(16) float s_vv[2][NHH*DD];
    __shared__ __align__(16) float s_h [2][DD];
    __shared__ __align__(16) float s_Vn[8][DD];
    __shared__ float s_zK[MM], s_zV[MM];
    __shared__ int   s_widx[2][8], s_ridx[2][8];
    __shared__ float s_dec[2][8], s_beta[2][2], s_inv[2][2];
    __shared__ float s_rel[8], s_attn[8];

    float4* KsB = (float4*)(Ks + (size_t)b * MM * DD);
    float4* VsB = (float4*)(Vs + (size_t)b * MM * DD);
    float*  zKb = zK + b * MM;
    float*  zVb = zV + b * MM;

    // big-operand staging for step t into buffer sb (896 float4 / 512 threads)
    auto stage = [&](int t, int sb) {
        int bt = b * TT + t;
        const float4* kj4 = (const float4*)(g_kj + (size_t)bt * NHH * DD);
        const float4* vk4 = (const float4*)(g_vk + (size_t)bt * NHH * DD);
        const float4* vv4 = (const float4*)(g_vv + (size_t)bt * NHH * DD);
        const float4* hh4 = (const float4*)(h    + (size_t)bt * DD);
#pragma unroll 2
        for (int f = tid; f < 896; f += 512) {
            if      (f < 256) ((float4*)s_kj[sb])[f]       = kj4[f];
            else if (f < 512) ((float4*)s_vk[sb])[f - 256] = vk4[f - 256];
            else if (f < 768) ((float4*)s_vv[sb])[f - 512] = vv4[f - 512];
            else              ((float4*)s_h [sb])[f - 768] = hh4[f - 768];
        }
    };
    auto stage_scalars = [&](int t, int sb) {
        int bt = b * TT + t;
        if (tid < 8) {
            s_widx[sb][tid] = g_widx[bt * TOPK + tid];
            s_ridx[sb][tid] = g_ridx[bt * TOPK + tid];
            s_dec [sb][tid] = g_dec [bt * TOPK + tid];
        } else if (tid < 10) {
            s_beta[sb][tid - 8] = g_beta[bt * NHH + tid - 8];
        } else if (tid < 12) {
            s_inv [sb][tid - 10] = g_kinv[bt * NHH + tid - 10];
        }
    };

    for (int i = tid; i < MM; i += 512) { s_zK[i] = zKb[i]; s_zV[i] = zVb[i]; }
    stage(0, 0);
    stage_scalars(0, 0);
    __syncthreads();

    for (int t = 0; t < TT; t++) {
        int bt = b * TT + t;
        int pb = t & 1;

        // stage next step's operands into the other buffer (hidden behind this step's compute)
        if (t + 1 < TT) { stage(t + 1, pb ^ 1); stage_scalars(t + 1, pb ^ 1); }

        // ---- write phase: decay + delta-rule on the 8 written slots ----
        {
            int   slot  = s_widx[pb][r];
            float decay = s_dec [pb][r];
            float4* base = (isV ? VsB : KsB) + slot * (DD / 4);
            float4 row[4];
#pragma unroll
            for (int i = 0; i < 4; i++) {
                float4 v = base[lane + 32 * i];
                row[i] = make_float4(v.x * decay, v.y * decay, v.z * decay, v.w * decay);
            }
            if (warp == 0 && lane < 8) {
                int sl = s_widx[pb][lane];
                float wl = g_ww[bt * TOPK + lane];
                float dl = s_dec[pb][lane];
                s_zK[sl] = dl * s_zK[sl] + wl;
                s_zV[sl] = dl * s_zV[sl] + wl;
            }
#pragma unroll
            for (int j = 0; j < NHH; j++) {
                float be   = s_beta[pb][j];
                float invj = s_inv [pb][j];
                const float4* KJ = (const float4*)&s_kj[pb][j * DD];
                const float4* VX = (const float4*)&((isV ? s_vv : s_vk)[pb][j * DD]);
                float4 kj4[4];
                float p = 0.f;
#pragma unroll
                for (int i = 0; i < 4; i++) {
                    kj4[i] = KJ[lane + 32 * i];
                    p += kj4[i].x * row[i].x + kj4[i].y * row[i].y
                       + kj4[i].z * row[i].z + kj4[i].w * row[i].w;
                }
#pragma unroll
                for (int o = 16; o > 0; o >>= 1) p += __shfl_xor_sync(0xffffffffu, p, o);
                // kh = kj*invj; row += be*kj*vx - be*(kh.row)*kh = be*kj*vx - be*invj^2*p*kj
                float cb = be * invj * invj * p;
#pragma unroll
                for (int i = 0; i < 4; i++) {
                    float4 vx4 = VX[lane + 32 * i];
                    row[i].x += be * kj4[i].x * vx4.x - cb * kj4[i].x;
                    row[i].y += be * kj4[i].y * vx4.y - cb * kj4[i].y;
                    row[i].z += be * kj4[i].z * vx4.z - cb * kj4[i].z;
                    row[i].w += be * kj4[i].w * vx4.w - cb * kj4[i].w;
                }
            }
#pragma unroll
            for (int i = 0; i < 4; i++) base[lane + 32 * i] = row[i];
        }
        __syncthreads();   // A: state stores + z updates + staged(t+1) visible

        // ---- read phase ----
        {
            int slot = s_ridx[pb][r];
            if (!isV) {
                const float4* base = KsB + slot * (DD / 4);
                const float4* H4   = (const float4*)s_h[pb];
                float p = 0.f;
#pragma unroll
                for (int i = 0; i < 4; i++) {
                    float4 k4 = base[lane + 32 * i];
                    float4 h4 = H4[lane + 32 * i];
                    p += k4.x * h4.x + k4.y * h4.y + k4.z * h4.z + k4.w * h4.w;
                }
#pragma unroll
                for (int o = 16; o > 0; o >>= 1) p += __shfl_xor_sync(0xffffffffu, p, o);
                if (lane == 0) s_rel[r] = p / s_zK[slot];
            } else {
                const float4* base = VsB + slot * (DD / 4);
                float invz = 1.0f / s_zV[slot];
                float4* dst = (float4*)s_Vn[r];
#pragma unroll
                for (int i = 0; i < 4; i++) {
                    float4 v = base[lane + 32 * i];
                    dst[lane + 32 * i] = make_float4(v.x * invz, v.y * invz, v.z * invz, v.w * invz);
                }
            }
        }
        __syncthreads();   // B: s_rel + s_Vn visible

        // ---- softmax over 8 rel values (warp 0) ----
        if (warp == 0) {
            float v = (lane < 8) ? s_rel[lane] * scale : -FLT_MAX;
            float m = v;
#pragma unroll
            for (int o = 16; o > 0; o >>= 1) m = fmaxf(m, __shfl_xor_sync(0xffffffffu, m, o));
            float e = (lane < 8) ? expf(v - m) : 0.f;
            float ssum = e;
#pragma unroll
            for (int o = 16; o > 0; o >>= 1) ssum += __shfl_xor_sync(0xffffffffu, ssum, o);
            if (lane < 8) s_attn[lane] = e / ssum;
        }
        __syncthreads();   // C: s_attn visible

        // ---- readout ----
        {
            float acc = 0.f;
#pragma unroll
            for (int i = 0; i < 8; i++) acc += s_attn[i] * s_Vn[i][tid];
            g_RO[(size_t)bt * DD + tid] = acc;
        }
    }

    __syncthreads();
    for (int i = tid; i < MM; i += 512) { zKb[i] = s_zK[i]; zVb[i] = s_zV[i]; }
}

// ---------------- final index outputs ----------------
__global__ void idxout_kernel(float* __restrict__ ow, float* __restrict__ orr)
{
    int k = threadIdx.x;
    if (k < BB * TOPK) {
        int b = k >> 3, q = k & 7;
        ow [k] = (float)g_widx[(b * TT + TT - 1) * TOPK + q];
        orr[k] = (float)g_ridx[(b * TT + TT - 1) * TOPK + q];
    }
}

// ---------------- launch ----------------
extern "C" void kernel_launch(void* const* d_in, const int* in_sizes, int n_in,
                              void* d_out, int out_size)
{
    const float* h      = (const float*)d_in[0];
    const float* Kslots = (const float*)d_in[1];
    const float* Vslots = (const float*)d_in[2];
    const float* zKin   = (const float*)d_in[3];
    const float* zVin   = (const float*)d_in[4];
    const float* W_k    = (const float*)d_in[5];
    const float* W_q    = (const float*)d_in[6];
    const float* ltw    = (const float*)d_in[7];
    const float* ltr    = (const float*)d_in[8];
    const float* hh_k   = (const float*)d_in[9];
    const float* hh_vk  = (const float*)d_in[10];
    const float* hh_vv  = (const float*)d_in[11];
    const float* hh_bw  = (const float*)d_in[12];
    const float* hh_bb  = (const float*)d_in[13];
    const float* gamma  = (const float*)d_in[14];
    const float* W_out  = (const float*)d_in[15];
    const float* W_gate = (const float*)d_in[16];

    float* out    = (float*)d_out;
    float* o_outs = out;
    float* o_K    = o_outs + (size_t)BB * TT * DD;
    float* o_V    = o_K    + (size_t)BB * MM * DD;
    float* o_zK   = o_V    + (size_t)BB * MM * DD;
    float* o_zV   = o_zK   + BB * MM;
    float* o_wi   = o_zV   + BB * MM;
    float* o_ri   = o_wi   + BB * TOPK;

    init_kernel<<<(BB * MM * DD + 255) / 256, 256>>>(Kslots, Vslots, zKin, zVin,
                                                     o_K, o_V, o_zK, o_zV);
    addr_kernel<<<BT, 64>>>(h, W_k, W_q, ltw, ltr);
    mega_gemm<<<dim3(28, 8), 256>>>(h, hh_k, hh_vk, hh_vv, W_gate);
    decay_kernel<<<(BT * TOPK + 255) / 256, 256>>>(gamma);
    norm_kernel<<<BT * NHH, 128>>>(h, hh_bw, hh_bb);

    seq_kernel<<<BB, 512>>>(h, o_K, o_V, o_zK, o_zV);

    out_gemm<<<dim3(8, 16), 256>>>(W_out, o_outs);
    idxout_kernel<<<1, 64>>>(o_wi, o_ri);
}